// round 2
// baseline (speedup 1.0000x reference)
#include <cuda_runtime.h>
#include <cuda_bf16.h>
#include <cstdint>

// EdgeBlock: out[e, :] = W @ concat(edges[e], nodes[recv[e]], nodes[send[e]]) + b
// E = 500000, NODE_D = EDGE_D = 128, IN_D = 384, W is [128, 384] row-major.
// NOTE: harness materializes int64 reference indices as int32 on device.

using ull = unsigned long long;

__device__ __forceinline__ ull pack_dup(float x) {
    ull r;
    asm("mov.b64 %0, {%1, %1};" : "=l"(r) : "f"(x));
    return r;
}
__device__ __forceinline__ void ffma2(ull& d, ull a, ull b) {
    // packed f32x2 fma: 2 MACs per instruction (full-rate vs half-rate 3-reg FFMA)
    asm("fma.rn.f32x2 %0, %1, %2, %0;" : "+l"(d) : "l"(a), "l"(b));
}
__device__ __forceinline__ void unpack2(ull v, float& lo, float& hi) {
    asm("mov.b64 {%0, %1}, %2;" : "=f"(lo), "=f"(hi) : "l"(v));
}

#define TE      128   // edges per CTA tile
#define KC      32    // K-chunk
#define NCHUNK  12    // 384 / 32
#define THREADS 256

__global__ void __launch_bounds__(THREADS, 2)
edgeblock_kernel(const float* __restrict__ nodes,
                 const float* __restrict__ edges,
                 const int* __restrict__ recv,
                 const int* __restrict__ send,
                 const float* __restrict__ W,
                 const float* __restrict__ bias,
                 float* __restrict__ out,
                 int E)
{
    __shared__ float Xs[TE][36];       // 128 x 32 (+pad to 36: f4-aligned rows)
    __shared__ float Ws[KC][132];      // 32 x 128 (+pad 4)
    __shared__ int Ridx[TE];
    __shared__ int Sidx[TE];

    const int t  = threadIdx.x;
    const int tx = t & 15;             // 16 output groups of 8
    const int ty = t >> 4;             // 16 edge groups of 8
    const int o_base = tx * 8;
    const int e_base = ty * 8;
    const int e0 = blockIdx.x * TE;

    // stage gather indices (guarded; clamp tail to node 0 — valid, unused)
    if (t < TE) {
        int e = e0 + t;
        Ridx[t] = (e < E) ? recv[e] : 0;
        Sidx[t] = (e < E) ? send[e] : 0;
    }

    // bias for this thread's 8 outputs
    float bb[8];
#pragma unroll
    for (int j = 0; j < 8; ++j) bb[j] = __ldg(&bias[o_base + j]);

    ull acc[8][4];
#pragma unroll
    for (int i = 0; i < 8; ++i)
#pragma unroll
        for (int j = 0; j < 4; ++j) acc[i][j] = 0ULL;

    __syncthreads();

    for (int c = 0; c < NCHUNK; ++c) {
        const int off = (c & 3) * KC;  // column offset within the source block

        // ---- stage Xs: 128 rows x 32 cols = 1024 float4, 4 per thread ----
#pragma unroll
        for (int i = 0; i < 4; ++i) {
            int idx = t + i * THREADS;
            int r = idx >> 3;          // tile row
            int q = idx & 7;           // float4 within row
            float4 v = make_float4(0.f, 0.f, 0.f, 0.f);
            if (c < 4) {
                int e = e0 + r;
                if (e < E) v = *reinterpret_cast<const float4*>(edges + (size_t)e * 128 + off + q * 4);
            } else if (c < 8) {
                v = *reinterpret_cast<const float4*>(nodes + (size_t)Ridx[r] * 128 + off + q * 4);
            } else {
                v = *reinterpret_cast<const float4*>(nodes + (size_t)Sidx[r] * 128 + off + q * 4);
            }
            *reinterpret_cast<float4*>(&Xs[r][q * 4]) = v;
        }

        // ---- stage Ws: W[o][c*32 + kk], coalesced along kk ----
        const int k0 = c * KC;
#pragma unroll
        for (int i = 0; i < 16; ++i) {
            int idx = t + i * THREADS;
            int o  = idx >> 5;
            int kk = idx & 31;
            Ws[kk][o] = __ldg(&W[(size_t)o * 384 + k0 + kk]);
        }

        __syncthreads();

        // ---- compute: 32 k-steps, 8x8 micro-tile via packed f32x2 FMA ----
#pragma unroll 4
        for (int kk = 0; kk < KC; ++kk) {
            ull bv[4];
            const ull* wp = reinterpret_cast<const ull*>(&Ws[kk][o_base]);
            bv[0] = wp[0]; bv[1] = wp[1]; bv[2] = wp[2]; bv[3] = wp[3];
#pragma unroll
            for (int i = 0; i < 8; ++i) {
                ull av = pack_dup(Xs[e_base + i][kk]);
                ffma2(acc[i][0], av, bv[0]);
                ffma2(acc[i][1], av, bv[1]);
                ffma2(acc[i][2], av, bv[2]);
                ffma2(acc[i][3], av, bv[3]);
            }
        }

        __syncthreads();
    }

    // ---- epilogue: unpack, add bias, store as float4 ----
#pragma unroll
    for (int i = 0; i < 8; ++i) {
        int e = e0 + e_base + i;
        if (e >= E) continue;
        float f[8];
#pragma unroll
        for (int j = 0; j < 4; ++j) unpack2(acc[i][j], f[2 * j], f[2 * j + 1]);
        float4 v0 = make_float4(f[0] + bb[0], f[1] + bb[1], f[2] + bb[2], f[3] + bb[3]);
        float4 v1 = make_float4(f[4] + bb[4], f[5] + bb[5], f[6] + bb[6], f[7] + bb[7]);
        float* op = out + (size_t)e * 128 + o_base;
        *reinterpret_cast<float4*>(op)     = v0;
        *reinterpret_cast<float4*>(op + 4) = v1;
    }
}

extern "C" void kernel_launch(void* const* d_in, const int* in_sizes, int n_in,
                              void* d_out, int out_size)
{
    const float* nodes = (const float*)d_in[0];
    const float* edges = (const float*)d_in[1];
    const int*   recv  = (const int*)d_in[2];
    const int*   send  = (const int*)d_in[3];
    const float* W     = (const float*)d_in[4];
    const float* bias  = (const float*)d_in[5];
    float*       out   = (float*)d_out;

    int E = in_sizes[2];               // number of edges (receivers count)
    int grid = (E + TE - 1) / TE;
    edgeblock_kernel<<<grid, THREADS>>>(nodes, edges, recv, send, W, bias, out, E);
}